// round 2
// baseline (speedup 1.0000x reference)
#include <cuda_runtime.h>
#include <math.h>

// Problem constants
#define BN 64
#define CN 64
#define HN 32
#define WN 32
#define KN 1024
#define NPTS (BN*HN*WN)          // 65536 points
#define PLANE (HN*WN)            // 1024
#define ZSZ (BN*CN*HN*WN)        // 4194304
#define EPSV 1e-10f

typedef unsigned long long ull;

__device__ float g_cnorm[KN];
__device__ int   g_hist[KN];

// ---------------------------------------------------------------------------
// Kernel 1: codebook squared norms, computed EXACTLY like XLA:
// sq = RN(e*e); sum sequential ascending c. Also zero the histogram.
// ---------------------------------------------------------------------------
__global__ void k_prep(const float* __restrict__ cb) {
    int k = blockIdx.x * blockDim.x + threadIdx.x;
    if (k >= KN) return;
    const float* row = cb + k * CN;
    float s = 0.0f;
    #pragma unroll
    for (int c = 0; c < CN; c++)
        s = __fadd_rn(s, __fmul_rn(row[c], row[c]));
    g_cnorm[k] = s;
    g_hist[k] = 0;
}

// ---------------------------------------------------------------------------
// Kernel 2: main distance + argmin + gather/writeback.
// Warp handles one (b,h) row; lane = w (one point per thread).
// Dot product per (n,k): STRICTLY SEQUENTIAL fused-FMA chain over ascending c
// (reproduces Eigen/XLA-CPU GEMM bit-exactly). f32x2 lanes carry TWO different
// codebook entries; 4 packed chains (8 k's) run concurrently for ILP.
// dist = RN(RN(||x||^2 + ||e||^2) - 2*dot), argmin = first minimum.
// ---------------------------------------------------------------------------
__global__ __launch_bounds__(128, 2)
void k_main(const float* __restrict__ z, const float* __restrict__ cb,
            float* __restrict__ out) {
    // sQ[quad q][c] : ulonglong2 = { (e_{4q}[c], e_{4q+1}[c]), (e_{4q+2}[c], e_{4q+3}[c]) }
    __shared__ ulonglong2 sQ[32 * 64];   // 32 quads (128 k) x 64 c = 32 KB
    __shared__ float sBN[128];

    const int lane = threadIdx.x & 31;
    const int warp = threadIdx.x >> 5;
    const int g = blockIdx.x * 4 + warp;       // (b,h) pair, 0..2047
    const int b = g >> 5;
    const int h = g & 31;

    const float* zp = z + (size_t)b * (CN * PLANE) + h * WN + lane;

    // Load point, duplicate each component into both f32x2 lanes, and compute
    // ||x||^2 sequentially (square rounds, then add rounds) ascending c.
    ull xd[64];
    float xnorm = 0.0f;
    #pragma unroll
    for (int c = 0; c < 64; c++) {
        float x = zp[c * PLANE];
        xnorm = __fadd_rn(xnorm, __fmul_rn(x, x));
        unsigned u = __float_as_uint(x);
        xd[c] = (ull)u | ((ull)u << 32);
    }

    float bestV = 3.4e38f;
    int   bestK = 0;

    for (int ch = 0; ch < KN; ch += 128) {
        __syncthreads();   // protect shared reuse
        // Stage 128 codebook rows, interleaved by k-pairs.
        {
            ull* sU = (ull*)sQ;
            const float* cbc = cb + (size_t)ch * CN;
            #pragma unroll
            for (int it = 0; it < 32; it++) {
                int i = threadIdx.x + it * 128;       // 0..4095
                int p = i >> 6;                       // k-pair 0..63
                int c = i & 63;
                float lo = cbc[(2 * p) * CN + c];
                float hi = cbc[(2 * p + 1) * CN + c];
                // destination: sQ[(p>>1)*64 + c], .x if p even else .y
                sU[(((p >> 1) * 64 + c) << 1) + (p & 1)] =
                    (ull)__float_as_uint(lo) | ((ull)__float_as_uint(hi) << 32);
            }
            if (threadIdx.x < 128) sBN[threadIdx.x] = g_cnorm[ch + threadIdx.x];
        }
        __syncthreads();

        // Process 2 quads (8 codebook entries) at a time: 4 packed chains.
        for (int q = 0; q < 32; q += 2) {
            const ulonglong2* e0 = &sQ[q * 64];
            const ulonglong2* e1 = &sQ[(q + 1) * 64];
            ull a0 = 0, a1 = 0, a2 = 0, a3 = 0;
            #pragma unroll
            for (int c = 0; c < 64; c++) {
                ulonglong2 A = e0[c];
                ulonglong2 B = e1[c];
                asm("fma.rn.f32x2 %0, %1, %2, %0;" : "+l"(a0) : "l"(xd[c]), "l"(A.x));
                asm("fma.rn.f32x2 %0, %1, %2, %0;" : "+l"(a1) : "l"(xd[c]), "l"(A.y));
                asm("fma.rn.f32x2 %0, %1, %2, %0;" : "+l"(a2) : "l"(xd[c]), "l"(B.x));
                asm("fma.rn.f32x2 %0, %1, %2, %0;" : "+l"(a3) : "l"(xd[c]), "l"(B.y));
            }
            float dots[8];
            dots[0] = __uint_as_float((unsigned)(a0 & 0xffffffffull));
            dots[1] = __uint_as_float((unsigned)(a0 >> 32));
            dots[2] = __uint_as_float((unsigned)(a1 & 0xffffffffull));
            dots[3] = __uint_as_float((unsigned)(a1 >> 32));
            dots[4] = __uint_as_float((unsigned)(a2 & 0xffffffffull));
            dots[5] = __uint_as_float((unsigned)(a2 >> 32));
            dots[6] = __uint_as_float((unsigned)(a3 & 0xffffffffull));
            dots[7] = __uint_as_float((unsigned)(a3 >> 32));
            const int kb = ch + q * 4;
            #pragma unroll
            for (int t = 0; t < 8; t++) {
                // s = RN(||x||^2 + ||e||^2);  d = RN(s - 2*dot)  (2*dot exact)
                float s = __fadd_rn(xnorm, sBN[q * 4 + t]);
                float d = __fadd_rn(s, __fmul_rn(-2.0f, dots[t]));
                if (d < bestV) { bestV = d; bestK = kb + t; }   // first-min ties
            }
        }
    }

    // ---- epilogue: histogram, indices, quantized / straight-through ----
    atomicAdd(&g_hist[bestK], 1);

    const int n = g * 32 + lane;                 // flat point index
    out[(size_t)2 * ZSZ + n] = (float)bestK;     // indices (as float)

    const float* crow = cb + (size_t)bestK * CN;
    float* q0 = out + (size_t)b * (CN * PLANE) + h * WN + lane;   // quantized_z
    float* q1 = q0 + (size_t)ZSZ;                                 // quantized_z_st
    #pragma unroll
    for (int c = 0; c < 64; c++) {
        float qv = crow[c];                                       // exact gather
        float xv = __uint_as_float((unsigned)(xd[c] & 0xffffffffull));
        q0[c * PLANE] = qv;
        q1[c * PLANE] = __fadd_rn(xv, __fsub_rn(qv, xv));         // z + (q - z)
    }
}

// ---------------------------------------------------------------------------
// Kernel 3: perplexity = exp(-sum p log(max(p, EPS)))
// ---------------------------------------------------------------------------
__global__ void k_perp(float* __restrict__ out) {
    __shared__ float red[32];
    int t = threadIdx.x;
    float p = (float)g_hist[t] * (1.0f / (float)NPTS);
    float term = __fmul_rn(p, logf(fmaxf(p, EPSV)));
    #pragma unroll
    for (int o = 16; o; o >>= 1) term += __shfl_xor_sync(0xffffffffu, term, o);
    if ((t & 31) == 0) red[t >> 5] = term;
    __syncthreads();
    if (t < 32) {
        float s = red[t];
        #pragma unroll
        for (int o = 16; o; o >>= 1) s += __shfl_xor_sync(0xffffffffu, s, o);
        if (t == 0) out[(size_t)2 * ZSZ + NPTS] = expf(-s);
    }
}

// ---------------------------------------------------------------------------
extern "C" void kernel_launch(void* const* d_in, const int* in_sizes, int n_in,
                              void* d_out, int out_size) {
    const float* z  = (const float*)d_in[0];
    const float* cb = (const float*)d_in[1];
    if (n_in >= 2 && in_sizes[0] == KN * CN && in_sizes[1] == ZSZ) {
        const float* t = z; z = cb; cb = t;   // defensive input-order swap
    }
    float* out = (float*)d_out;

    k_prep<<<8, 128>>>(cb);
    k_main<<<512, 128>>>(z, cb, out);
    k_perp<<<1, 1024>>>(out);
    (void)out_size;
}